// round 1
// baseline (speedup 1.0000x reference)
#include <cuda_runtime.h>
#include <math.h>

#define BATCH 4096
#define FEAT  40960
#define HID   1024
#define HID2  2048
#define NL1   64
#define NL2   32

// ---------------- scratch (static device memory: allowed) ----------------
__device__ float g_h1[(size_t)BATCH * HID2];   // clipped feature-transformer output

// =========================================================================
// Kernel 1: sparse feature transformer.
// One CTA per batch row. 256 threads. Thread t owns HID columns {t, t+256, t+512, t+768}.
// =========================================================================
#define T1 256
#define MAXIDX 2048

__global__ __launch_bounds__(T1) void ft_kernel(
    const float* __restrict__ wf,    // [B, FEAT]
    const float* __restrict__ bfeat, // [B, FEAT]
    const float* __restrict__ stm,   // [B, 1]
    const float* __restrict__ ft_w,  // [HID, FEAT]^T view: row-major [HID, FEAT]?? NO: ft_w is [HID, FEAT]
    const float* __restrict__ ft_b)  // [HID]
{
    // NOTE: reference does features @ ft_w.T with ft_w [HID, FEAT] row-major.
    // So output[h] = sum_f feat[f] * ft_w[h, f]. Column gather of ft_w would be
    // strided; instead we use: for active f, add ft_w[:, f]. ft_w[h, f] is at
    // h*FEAT + f  -> stride-FEAT gather (bad). BUT ft_w is [HID=1024, FEAT=40960]
    // row-major, so the column f is strided. To keep loads coalesced we instead
    // read ft_w transposed on the fly per active feature:
    //   acc[h] += ft_w[h*FEAT + f]
    // Consecutive threads (consecutive h) -> addresses stride FEAT*4 bytes: NOT coalesced.
    // Fix: treat gather as 32B-sector loads; with ~123k gathers x 1024 h this would
    // explode. Instead we flip the ownership: thread t owns h = t + 256k, and we
    // accept the strided gather BUT route it through __ldg with FEAT stride.
    // -> See loop below; L2 working set is ft_w (167MB), hit-rate dominated.
    __shared__ int s_idx[MAXIDX];
    __shared__ int s_cnt;

    const int b   = blockIdx.x;
    const int tid = threadIdx.x;

    float accW[4], accB[4];
#pragma unroll
    for (int k = 0; k < 4; k++) {
        float bb = __ldg(ft_b + tid + 256 * k);
        accW[k] = bb;
        accB[k] = bb;
    }

    // ---------- pass 1: white ----------
    if (tid == 0) s_cnt = 0;
    __syncthreads();
    {
        const float4* p = (const float4*)(wf + (size_t)b * FEAT);
#pragma unroll 4
        for (int i = tid; i < FEAT / 4; i += T1) {
            float4 v = p[i];
            if (v.x != 0.f) { int q = atomicAdd(&s_cnt, 1); if (q < MAXIDX) s_idx[q] = 4*i;   }
            if (v.y != 0.f) { int q = atomicAdd(&s_cnt, 1); if (q < MAXIDX) s_idx[q] = 4*i+1; }
            if (v.z != 0.f) { int q = atomicAdd(&s_cnt, 1); if (q < MAXIDX) s_idx[q] = 4*i+2; }
            if (v.w != 0.f) { int q = atomicAdd(&s_cnt, 1); if (q < MAXIDX) s_idx[q] = 4*i+3; }
        }
    }
    __syncthreads();
    {
        int n = min(s_cnt, MAXIDX);
        for (int j = 0; j < n; j++) {
            const float* col = ft_w + s_idx[j];   // ft_w[h, f] = ft_w[h*FEAT + f]
#pragma unroll
            for (int k = 0; k < 4; k++)
                accW[k] += __ldg(col + (size_t)(tid + 256 * k) * FEAT);
        }
    }
    __syncthreads();

    // ---------- pass 2: black ----------
    if (tid == 0) s_cnt = 0;
    __syncthreads();
    {
        const float4* p = (const float4*)(bfeat + (size_t)b * FEAT);
#pragma unroll 4
        for (int i = tid; i < FEAT / 4; i += T1) {
            float4 v = p[i];
            if (v.x != 0.f) { int q = atomicAdd(&s_cnt, 1); if (q < MAXIDX) s_idx[q] = 4*i;   }
            if (v.y != 0.f) { int q = atomicAdd(&s_cnt, 1); if (q < MAXIDX) s_idx[q] = 4*i+1; }
            if (v.z != 0.f) { int q = atomicAdd(&s_cnt, 1); if (q < MAXIDX) s_idx[q] = 4*i+2; }
            if (v.w != 0.f) { int q = atomicAdd(&s_cnt, 1); if (q < MAXIDX) s_idx[q] = 4*i+3; }
        }
    }
    __syncthreads();
    {
        int n = min(s_cnt, MAXIDX);
        for (int j = 0; j < n; j++) {
            const float* col = ft_w + s_idx[j];
#pragma unroll
            for (int k = 0; k < 4; k++)
                accB[k] += __ldg(col + (size_t)(tid + 256 * k) * FEAT);
        }
    }

    // ---------- stm select + clip + store ----------
    const float s = __ldg(stm + b);         // 0.0 or 1.0
    float* o = g_h1 + (size_t)b * HID2;
#pragma unroll
    for (int k = 0; k < 4; k++) {
        float cw = fminf(fmaxf(accW[k], 0.f), 1.f);
        float cb = fminf(fmaxf(accB[k], 0.f), 1.f);
        float first  = s * cw + (1.f - s) * cb;
        float second = s * cb + (1.f - s) * cw;
        o[tid + 256 * k]        = first;
        o[HID + tid + 256 * k]  = second;
    }
}

// =========================================================================
// Kernel 2: MLP head (l1 64x2048 -> clip -> l2 32x64 -> clip -> l3 1x32 -> sigmoid)
// TB=32 batch rows / CTA, 256 threads, 4 rows x 2 outs register tiles.
// =========================================================================
#define T2    256
#define TB    32
#define CHUNK 64

__global__ __launch_bounds__(T2) void mlp_kernel(
    const float* __restrict__ l1_w, const float* __restrict__ l1_b,
    const float* __restrict__ l2_w, const float* __restrict__ l2_b,
    const float* __restrict__ l3_w, const float* __restrict__ l3_b,
    float* __restrict__ out, int out_size)
{
    __shared__ float hs[TB][CHUNK + 1];      // 32*65*4 = 8.3 KB (h1 chunk; later h3)
    __shared__ float ws[NL1][CHUNK + 1];     // 64*65*4 = 16.6 KB (l1_w chunk; later h2)
    __shared__ float l2s[NL2][NL1 + 1];      // 32*65*4 = 8.3 KB
    __shared__ float l3s[NL2];

    const int tid  = threadIdx.x;
    const int row0 = blockIdx.x * TB;
    const int tx   = tid & 31;   // out pair: {2tx, 2tx+1}
    const int ty   = tid >> 5;   // row quad: {4ty..4ty+3}

    // preload small weights
    for (int i = tid; i < NL2 * NL1; i += T2) l2s[i >> 6][i & 63] = l2_w[i];
    if (tid < NL2) l3s[tid] = l3_w[tid];

    float acc[4][2];
#pragma unroll
    for (int i = 0; i < 4; i++) { acc[i][0] = 0.f; acc[i][1] = 0.f; }

    for (int kc = 0; kc < HID2; kc += CHUNK) {
        __syncthreads();
        // stage h1 tile chunk: [TB][CHUNK]
        for (int idx = tid; idx < TB * CHUNK; idx += T2) {
            int r = idx >> 6, kk = idx & 63;
            hs[r][kk] = g_h1[(size_t)(row0 + r) * HID2 + kc + kk];
        }
        // stage l1_w chunk: [NL1][CHUNK]
        for (int idx = tid; idx < NL1 * CHUNK; idx += T2) {
            int oo = idx >> 6, kk = idx & 63;
            ws[oo][kk] = __ldg(l1_w + (size_t)oo * HID2 + kc + kk);
        }
        __syncthreads();
#pragma unroll 8
        for (int k = 0; k < CHUNK; k++) {
            float h0 = hs[4 * ty + 0][k];
            float h1 = hs[4 * ty + 1][k];
            float h2 = hs[4 * ty + 2][k];
            float h3 = hs[4 * ty + 3][k];
            float w0 = ws[2 * tx + 0][k];
            float w1 = ws[2 * tx + 1][k];
            acc[0][0] = fmaf(h0, w0, acc[0][0]); acc[0][1] = fmaf(h0, w1, acc[0][1]);
            acc[1][0] = fmaf(h1, w0, acc[1][0]); acc[1][1] = fmaf(h1, w1, acc[1][1]);
            acc[2][0] = fmaf(h2, w0, acc[2][0]); acc[2][1] = fmaf(h2, w1, acc[2][1]);
            acc[3][0] = fmaf(h3, w0, acc[3][0]); acc[3][1] = fmaf(h3, w1, acc[3][1]);
        }
    }
    __syncthreads();

    // h2 -> ws[row][out]  (rows 0..31, outs 0..63; ws has 64 rows so it fits)
#pragma unroll
    for (int i = 0; i < 4; i++) {
#pragma unroll
        for (int j = 0; j < 2; j++) {
            float v = acc[i][j] + __ldg(l1_b + 2 * tx + j);
            ws[4 * ty + i][2 * tx + j] = fminf(fmaxf(v, 0.f), 1.f);
        }
    }
    __syncthreads();

    // l2: h3[row][o] -> hs[row][o]   (TB*NL2 = 1024 pairs, 4 per thread)
    for (int p = tid; p < TB * NL2; p += T2) {
        int r = p >> 5, oo = p & 31;
        float s = __ldg(l2_b + oo);
#pragma unroll
        for (int k = 0; k < NL1; k++) s = fmaf(ws[r][k], l2s[oo][k], s);
        hs[r][oo] = fminf(fmaxf(s, 0.f), 1.f);
    }
    __syncthreads();

    // l3 + sigmoid
    if (tid < TB) {
        float s = __ldg(l3_b);
#pragma unroll
        for (int k = 0; k < NL2; k++) s = fmaf(hs[tid][k], l3s[k], s);
        float sig = 1.f / (1.f + expf(-s));
        int r = row0 + tid;
        if (out_size >= 2 * BATCH) {
            out[r]         = sig;   // sigmoid(raw)
            out[BATCH + r] = s;     // raw
        } else {
            out[r] = sig;
        }
    }
}

// =========================================================================
extern "C" void kernel_launch(void* const* d_in, const int* in_sizes, int n_in,
                              void* d_out, int out_size)
{
    const float* wf    = (const float*)d_in[0];  // white_features [B, FEAT]
    const float* bfeat = (const float*)d_in[1];  // black_features [B, FEAT]
    const float* stm   = (const float*)d_in[2];  // [B, 1]
    const float* ft_w  = (const float*)d_in[3];  // [HID, FEAT]
    const float* ft_b  = (const float*)d_in[4];  // [HID]
    const float* l1_w  = (const float*)d_in[5];  // [64, 2048]
    const float* l1_b  = (const float*)d_in[6];  // [64]
    const float* l2_w  = (const float*)d_in[7];  // [32, 64]
    const float* l2_b  = (const float*)d_in[8];  // [32]
    const float* l3_w  = (const float*)d_in[9];  // [1, 32]
    const float* l3_b  = (const float*)d_in[10]; // [1]
    float* out = (float*)d_out;

    ft_kernel<<<BATCH, T1>>>(wf, bfeat, stm, ft_w, ft_b);
    mlp_kernel<<<BATCH / TB, T2>>>(l1_w, l1_b, l2_w, l2_b, l3_w, l3_b, out, out_size);
}

// round 2
// speedup vs baseline: 6.3592x; 6.3592x over previous
#include <cuda_runtime.h>
#include <math.h>

#define BATCH 4096
#define FEAT  40960
#define HID   1024
#define HID2  2048
#define NL1   64
#define NL2   32

// ---------------- static device scratch (no allocs allowed) ----------------
__device__ float g_h1[(size_t)BATCH * HID2];     // 33.5 MB: clipped FT output
__device__ float g_ftT[(size_t)FEAT * HID];      // 167.8 MB: ft_w transposed [FEAT][HID]

// =========================================================================
// Kernel 0: transpose ft_w [HID, FEAT] -> g_ftT [FEAT, HID]
// =========================================================================
__global__ __launch_bounds__(256) void transpose_ftw(const float* __restrict__ src)
{
    __shared__ float tile[32][33];
    const int f0 = blockIdx.x * 32;
    const int h0 = blockIdx.y * 32;
    const int tx = threadIdx.x;          // 0..31
    const int ty = threadIdx.y;          // 0..7
#pragma unroll
    for (int i = 0; i < 4; i++)
        tile[ty + 8 * i][tx] = src[(size_t)(h0 + ty + 8 * i) * FEAT + f0 + tx];
    __syncthreads();
#pragma unroll
    for (int i = 0; i < 4; i++)
        g_ftT[(size_t)(f0 + ty + 8 * i) * HID + h0 + tx] = tile[tx][ty + 8 * i];
}

// =========================================================================
// Kernel 1: sparse feature transformer (coalesced gather from g_ftT).
// One CTA per batch row, 256 threads. Thread t owns h = 4t..4t+3 (float4).
// =========================================================================
#define T1 256
#define MAXIDX 2048

__global__ __launch_bounds__(T1) void ft_kernel(
    const float* __restrict__ wf,    // [B, FEAT]
    const float* __restrict__ bfeat, // [B, FEAT]
    const float* __restrict__ stm,   // [B, 1]
    const float* __restrict__ ft_b)  // [HID]
{
    __shared__ int s_idx[MAXIDX];
    __shared__ int s_cnt;

    const int b   = blockIdx.x;
    const int tid = threadIdx.x;

    const float4 bias = *reinterpret_cast<const float4*>(ft_b + 4 * tid);
    float4 accW = bias, accB = bias;

    // ---------- scan white ----------
    if (tid == 0) s_cnt = 0;
    __syncthreads();
    {
        const float4* p = (const float4*)(wf + (size_t)b * FEAT);
#pragma unroll 4
        for (int i = tid; i < FEAT / 4; i += T1) {
            float4 v = p[i];
            if (v.x != 0.f) { int q = atomicAdd(&s_cnt, 1); if (q < MAXIDX) s_idx[q] = 4*i;   }
            if (v.y != 0.f) { int q = atomicAdd(&s_cnt, 1); if (q < MAXIDX) s_idx[q] = 4*i+1; }
            if (v.z != 0.f) { int q = atomicAdd(&s_cnt, 1); if (q < MAXIDX) s_idx[q] = 4*i+2; }
            if (v.w != 0.f) { int q = atomicAdd(&s_cnt, 1); if (q < MAXIDX) s_idx[q] = 4*i+3; }
        }
    }
    __syncthreads();
    {
        const int n = min(s_cnt, MAXIDX);
#pragma unroll 4
        for (int j = 0; j < n; j++) {
            const float4 w = *reinterpret_cast<const float4*>(
                g_ftT + (size_t)s_idx[j] * HID + 4 * tid);
            accW.x += w.x; accW.y += w.y; accW.z += w.z; accW.w += w.w;
        }
    }
    __syncthreads();

    // ---------- scan black ----------
    if (tid == 0) s_cnt = 0;
    __syncthreads();
    {
        const float4* p = (const float4*)(bfeat + (size_t)b * FEAT);
#pragma unroll 4
        for (int i = tid; i < FEAT / 4; i += T1) {
            float4 v = p[i];
            if (v.x != 0.f) { int q = atomicAdd(&s_cnt, 1); if (q < MAXIDX) s_idx[q] = 4*i;   }
            if (v.y != 0.f) { int q = atomicAdd(&s_cnt, 1); if (q < MAXIDX) s_idx[q] = 4*i+1; }
            if (v.z != 0.f) { int q = atomicAdd(&s_cnt, 1); if (q < MAXIDX) s_idx[q] = 4*i+2; }
            if (v.w != 0.f) { int q = atomicAdd(&s_cnt, 1); if (q < MAXIDX) s_idx[q] = 4*i+3; }
        }
    }
    __syncthreads();
    {
        const int n = min(s_cnt, MAXIDX);
#pragma unroll 4
        for (int j = 0; j < n; j++) {
            const float4 w = *reinterpret_cast<const float4*>(
                g_ftT + (size_t)s_idx[j] * HID + 4 * tid);
            accB.x += w.x; accB.y += w.y; accB.z += w.z; accB.w += w.w;
        }
    }

    // ---------- stm select + clip + store ----------
    const float s = __ldg(stm + b);         // 0.0 or 1.0
    float* o = g_h1 + (size_t)b * HID2;
    float4 cw, cb;
    cw.x = fminf(fmaxf(accW.x, 0.f), 1.f); cw.y = fminf(fmaxf(accW.y, 0.f), 1.f);
    cw.z = fminf(fmaxf(accW.z, 0.f), 1.f); cw.w = fminf(fmaxf(accW.w, 0.f), 1.f);
    cb.x = fminf(fmaxf(accB.x, 0.f), 1.f); cb.y = fminf(fmaxf(accB.y, 0.f), 1.f);
    cb.z = fminf(fmaxf(accB.z, 0.f), 1.f); cb.w = fminf(fmaxf(accB.w, 0.f), 1.f);
    float4 first, second;
    first.x  = s * cw.x + (1.f - s) * cb.x;  second.x = s * cb.x + (1.f - s) * cw.x;
    first.y  = s * cw.y + (1.f - s) * cb.y;  second.y = s * cb.y + (1.f - s) * cw.y;
    first.z  = s * cw.z + (1.f - s) * cb.z;  second.z = s * cb.z + (1.f - s) * cw.z;
    first.w  = s * cw.w + (1.f - s) * cb.w;  second.w = s * cb.w + (1.f - s) * cw.w;
    *reinterpret_cast<float4*>(o + 4 * tid)        = first;
    *reinterpret_cast<float4*>(o + HID + 4 * tid)  = second;
}

// =========================================================================
// Kernel 2: MLP head. TB=32 rows/CTA, 256 threads, 4 rows x 2 outs per thread.
// Transposed smem tiles (float4 broadcast + float2 loads), register-staged
// double buffering: one barrier per chunk.
// =========================================================================
#define T2    256
#define TB    32
#define CHUNK 64
#define NCH   (HID2 / CHUNK)   // 32
#define HPAD  36               // stride 144B: 16B-aligned, conflict-tolerable
#define WPAD  66               // stride 264B: 8B-aligned, 2-way on store

__global__ __launch_bounds__(T2) void mlp_kernel(
    const float* __restrict__ l1_w, const float* __restrict__ l1_b,
    const float* __restrict__ l2_w, const float* __restrict__ l2_b,
    const float* __restrict__ l3_w, const float* __restrict__ l3_b,
    float* __restrict__ out, int out_size)
{
    __shared__ __align__(16) float hst[2][CHUNK][HPAD];   // 18.4 KB
    __shared__ __align__(16) float wst[2][CHUNK][WPAD];   // 33.8 KB
    __shared__ float l2s[NL2][NL1 + 1];                   // 8.3 KB
    __shared__ float h2s[TB][NL1 + 1];                    // 8.3 KB
    __shared__ float h3s[TB][NL2 + 1];                    // 4.2 KB
    __shared__ float l3s[NL2];

    const int tid  = threadIdx.x;
    const int row0 = blockIdx.x * TB;
    const int tx   = tid & 31;   // out pair {2tx, 2tx+1}
    const int ty   = tid >> 5;   // row quad {4ty..4ty+3}

    for (int i = tid; i < NL2 * NL1; i += T2) l2s[i >> 6][i & 63] = l2_w[i];
    if (tid < NL2) l3s[tid] = l3_w[tid];

    float hreg[8], wreg[16];
    // stage chunk 0
    {
        const int kc = 0;
#pragma unroll
        for (int u = 0; u < 8; u++) {
            int idx = tid + u * T2; int r = idx >> 6, kk = idx & 63;
            hreg[u] = g_h1[(size_t)(row0 + r) * HID2 + kc + kk];
        }
#pragma unroll
        for (int u = 0; u < 16; u++) {
            int idx = tid + u * T2; int oo = idx >> 6, kk = idx & 63;
            wreg[u] = __ldg(l1_w + (size_t)oo * HID2 + kc + kk);
        }
#pragma unroll
        for (int u = 0; u < 8; u++) {
            int idx = tid + u * T2; int r = idx >> 6, kk = idx & 63;
            hst[0][kk][r] = hreg[u];
        }
#pragma unroll
        for (int u = 0; u < 16; u++) {
            int idx = tid + u * T2; int oo = idx >> 6, kk = idx & 63;
            wst[0][kk][oo] = wreg[u];
        }
    }
    __syncthreads();

    float acc[4][2];
#pragma unroll
    for (int i = 0; i < 4; i++) { acc[i][0] = 0.f; acc[i][1] = 0.f; }

    for (int c = 0; c < NCH; c++) {
        const int buf = c & 1;
        // issue next-chunk global loads before compute
        if (c + 1 < NCH) {
            const int kc = (c + 1) * CHUNK;
#pragma unroll
            for (int u = 0; u < 8; u++) {
                int idx = tid + u * T2; int r = idx >> 6, kk = idx & 63;
                hreg[u] = g_h1[(size_t)(row0 + r) * HID2 + kc + kk];
            }
#pragma unroll
            for (int u = 0; u < 16; u++) {
                int idx = tid + u * T2; int oo = idx >> 6, kk = idx & 63;
                wreg[u] = __ldg(l1_w + (size_t)oo * HID2 + kc + kk);
            }
        }
        // compute on current buffer
#pragma unroll 16
        for (int k = 0; k < CHUNK; k++) {
            const float4 h = *reinterpret_cast<const float4*>(&hst[buf][k][4 * ty]);
            const float2 w = *reinterpret_cast<const float2*>(&wst[buf][k][2 * tx]);
            acc[0][0] = fmaf(h.x, w.x, acc[0][0]); acc[0][1] = fmaf(h.x, w.y, acc[0][1]);
            acc[1][0] = fmaf(h.y, w.x, acc[1][0]); acc[1][1] = fmaf(h.y, w.y, acc[1][1]);
            acc[2][0] = fmaf(h.z, w.x, acc[2][0]); acc[2][1] = fmaf(h.z, w.y, acc[2][1]);
            acc[3][0] = fmaf(h.w, w.x, acc[3][0]); acc[3][1] = fmaf(h.w, w.y, acc[3][1]);
        }
        // store next chunk into other buffer
        if (c + 1 < NCH) {
            const int nb = (c + 1) & 1;
#pragma unroll
            for (int u = 0; u < 8; u++) {
                int idx = tid + u * T2; int r = idx >> 6, kk = idx & 63;
                hst[nb][kk][r] = hreg[u];
            }
#pragma unroll
            for (int u = 0; u < 16; u++) {
                int idx = tid + u * T2; int oo = idx >> 6, kk = idx & 63;
                wst[nb][kk][oo] = wreg[u];
            }
        }
        __syncthreads();
    }

    // h2 = clip(l1 out + bias) -> h2s[row][out]
#pragma unroll
    for (int i = 0; i < 4; i++) {
#pragma unroll
        for (int j = 0; j < 2; j++) {
            float v = acc[i][j] + __ldg(l1_b + 2 * tx + j);
            h2s[4 * ty + i][2 * tx + j] = fminf(fmaxf(v, 0.f), 1.f);
        }
    }
    __syncthreads();

    // l2: h3[row][o]
    for (int p = tid; p < TB * NL2; p += T2) {
        int r = p >> 5, oo = p & 31;
        float s = __ldg(l2_b + oo);
#pragma unroll
        for (int k = 0; k < NL1; k++) s = fmaf(h2s[r][k], l2s[oo][k], s);
        h3s[r][oo] = fminf(fmaxf(s, 0.f), 1.f);
    }
    __syncthreads();

    // l3 + sigmoid
    if (tid < TB) {
        float s = __ldg(l3_b);
#pragma unroll
        for (int k = 0; k < NL2; k++) s = fmaf(h3s[tid][k], l3s[k], s);
        float sig = 1.f / (1.f + expf(-s));
        int r = row0 + tid;
        if (out_size >= 2 * BATCH) {
            out[r]         = sig;   // sigmoid(raw)
            out[BATCH + r] = s;     // raw
        } else {
            out[r] = sig;
        }
    }
}

// =========================================================================
extern "C" void kernel_launch(void* const* d_in, const int* in_sizes, int n_in,
                              void* d_out, int out_size)
{
    const float* wf    = (const float*)d_in[0];
    const float* bfeat = (const float*)d_in[1];
    const float* stm   = (const float*)d_in[2];
    const float* ft_w  = (const float*)d_in[3];
    const float* ft_b  = (const float*)d_in[4];
    const float* l1_w  = (const float*)d_in[5];
    const float* l1_b  = (const float*)d_in[6];
    const float* l2_w  = (const float*)d_in[7];
    const float* l2_b  = (const float*)d_in[8];
    const float* l3_w  = (const float*)d_in[9];
    const float* l3_b  = (const float*)d_in[10];
    float* out = (float*)d_out;

    dim3 tgrid(FEAT / 32, HID / 32);
    dim3 tblk(32, 8);
    transpose_ftw<<<tgrid, tblk>>>(ft_w);
    ft_kernel<<<BATCH, T1>>>(wf, bfeat, stm, ft_b);
    mlp_kernel<<<BATCH / TB, T2>>>(l1_w, l1_b, l2_w, l2_b, l3_w, l3_b, out, out_size);
}

// round 3
// speedup vs baseline: 7.8594x; 1.2359x over previous
#include <cuda_runtime.h>
#include <cuda_fp16.h>
#include <math.h>

#define BATCH 4096
#define FEAT  40960
#define HID   1024
#define HID2  2048
#define NL1   64
#define NL2   32

// ---------------- static device scratch (no allocs allowed) ----------------
__device__ __half g_h1[(size_t)BATCH * HID2];     // 16.8 MB: clipped FT output (fp16)
__device__ __half g_ftT[(size_t)FEAT * HID];      // 83.9 MB: ft_w transposed [FEAT][HID] (fp16) -> L2-resident

// =========================================================================
// Kernel 0: transpose ft_w [HID, FEAT] fp32 -> g_ftT [FEAT, HID] fp16
// Tile: 64 h x 32 f per CTA (256 threads).
// =========================================================================
__global__ __launch_bounds__(256) void transpose_ftw(const float* __restrict__ src)
{
    __shared__ float tile[64][33];
    const int f0  = blockIdx.x * 32;
    const int h0  = blockIdx.y * 64;
    const int tid = threadIdx.x;

    // load 64h x 32f, coalesced in f (streamed once -> evict-first)
#pragma unroll
    for (int u = 0; u < 8; u++) {
        int idx = tid + u * 256;
        int hl = idx >> 5, fl = idx & 31;
        tile[hl][fl] = __ldcs(src + (size_t)(h0 + hl) * FEAT + f0 + fl);
    }
    __syncthreads();

    // write 32f x 64h as half2, coalesced in h
#pragma unroll
    for (int u = 0; u < 4; u++) {
        int idx = tid + u * 256;
        int fl = idx >> 5, hp = idx & 31;
        __half2 v = __floats2half2_rn(tile[2 * hp][fl], tile[2 * hp + 1][fl]);
        *reinterpret_cast<__half2*>(g_ftT + (size_t)(f0 + fl) * HID + h0 + 2 * hp) = v;
    }
}

// =========================================================================
// Kernel 1: sparse feature transformer.
// One CTA per batch row, 256 threads. Thread t owns h = 4t..4t+3.
// Scan with batched streaming float4 loads; gather fp16 rows from g_ftT (L2).
// =========================================================================
#define T1 256
#define MAXIDX 2048

__device__ __forceinline__ void scan_features(const float* __restrict__ feat,
                                              int b, int tid,
                                              int* s_idx, int* s_cnt)
{
    const float4* p = (const float4*)(feat + (size_t)b * FEAT);
    // FEAT/4 = 10240 float4; 256 threads -> 40 each; batch 4 loads per iter.
    for (int base = 0; base < FEAT / 4; base += 4 * T1) {
        float4 v[4];
#pragma unroll
        for (int u = 0; u < 4; u++)
            v[u] = __ldcs(p + base + tid + u * T1);
#pragma unroll
        for (int u = 0; u < 4; u++) {
            int i = base + tid + u * T1;
            if (v[u].x != 0.f) { int q = atomicAdd(s_cnt, 1); if (q < MAXIDX) s_idx[q] = 4*i;   }
            if (v[u].y != 0.f) { int q = atomicAdd(s_cnt, 1); if (q < MAXIDX) s_idx[q] = 4*i+1; }
            if (v[u].z != 0.f) { int q = atomicAdd(s_cnt, 1); if (q < MAXIDX) s_idx[q] = 4*i+2; }
            if (v[u].w != 0.f) { int q = atomicAdd(s_cnt, 1); if (q < MAXIDX) s_idx[q] = 4*i+3; }
        }
    }
}

__device__ __forceinline__ void gather_rows(const int* s_idx, int n, int tid,
                                            float4* acc)
{
#pragma unroll 4
    for (int j = 0; j < n; j++) {
        const uint2 raw = *reinterpret_cast<const uint2*>(
            g_ftT + (size_t)s_idx[j] * HID + 4 * tid);
        const float2 lo = __half22float2(*reinterpret_cast<const __half2*>(&raw.x));
        const float2 hi = __half22float2(*reinterpret_cast<const __half2*>(&raw.y));
        acc->x += lo.x; acc->y += lo.y; acc->z += hi.x; acc->w += hi.y;
    }
}

__global__ __launch_bounds__(T1) void ft_kernel(
    const float* __restrict__ wf,    // [B, FEAT]
    const float* __restrict__ bfeat, // [B, FEAT]
    const float* __restrict__ stm,   // [B, 1]
    const float* __restrict__ ft_b)  // [HID]
{
    __shared__ int s_idx[MAXIDX];
    __shared__ int s_cnt;

    const int b   = blockIdx.x;
    const int tid = threadIdx.x;

    const float4 bias = *reinterpret_cast<const float4*>(ft_b + 4 * tid);
    float4 accW = bias, accB = bias;

    // ---------- white ----------
    if (tid == 0) s_cnt = 0;
    __syncthreads();
    scan_features(wf, b, tid, s_idx, &s_cnt);
    __syncthreads();
    gather_rows(s_idx, min(s_cnt, MAXIDX), tid, &accW);
    __syncthreads();

    // ---------- black ----------
    if (tid == 0) s_cnt = 0;
    __syncthreads();
    scan_features(bfeat, b, tid, s_idx, &s_cnt);
    __syncthreads();
    gather_rows(s_idx, min(s_cnt, MAXIDX), tid, &accB);

    // ---------- stm select + clip + store fp16 ----------
    const float s = __ldg(stm + b);         // 0.0 or 1.0
    float4 cw, cb;
    cw.x = fminf(fmaxf(accW.x, 0.f), 1.f); cw.y = fminf(fmaxf(accW.y, 0.f), 1.f);
    cw.z = fminf(fmaxf(accW.z, 0.f), 1.f); cw.w = fminf(fmaxf(accW.w, 0.f), 1.f);
    cb.x = fminf(fmaxf(accB.x, 0.f), 1.f); cb.y = fminf(fmaxf(accB.y, 0.f), 1.f);
    cb.z = fminf(fmaxf(accB.z, 0.f), 1.f); cb.w = fminf(fmaxf(accB.w, 0.f), 1.f);

    float4 first, second;
    first.x  = s * cw.x + (1.f - s) * cb.x;  second.x = s * cb.x + (1.f - s) * cw.x;
    first.y  = s * cw.y + (1.f - s) * cb.y;  second.y = s * cb.y + (1.f - s) * cw.y;
    first.z  = s * cw.z + (1.f - s) * cb.z;  second.z = s * cb.z + (1.f - s) * cw.z;
    first.w  = s * cw.w + (1.f - s) * cb.w;  second.w = s * cb.w + (1.f - s) * cw.w;

    __half* o = g_h1 + (size_t)b * HID2;
    uint2 pf, ps;
    *reinterpret_cast<__half2*>(&pf.x) = __floats2half2_rn(first.x, first.y);
    *reinterpret_cast<__half2*>(&pf.y) = __floats2half2_rn(first.z, first.w);
    *reinterpret_cast<__half2*>(&ps.x) = __floats2half2_rn(second.x, second.y);
    *reinterpret_cast<__half2*>(&ps.y) = __floats2half2_rn(second.z, second.w);
    *reinterpret_cast<uint2*>(o + 4 * tid)       = pf;
    *reinterpret_cast<uint2*>(o + HID + 4 * tid) = ps;
}

// =========================================================================
// Kernel 2: MLP head. TB=32 rows/CTA, 256 threads, 4 rows x 2 outs per thread.
// h1 read as fp16, compute fp32. Register-staged double buffering.
// =========================================================================
#define T2    256
#define TB    32
#define CHUNK 64
#define NCH   (HID2 / CHUNK)   // 32
#define HPAD  36
#define WPAD  66

__global__ __launch_bounds__(T2) void mlp_kernel(
    const float* __restrict__ l1_w, const float* __restrict__ l1_b,
    const float* __restrict__ l2_w, const float* __restrict__ l2_b,
    const float* __restrict__ l3_w, const float* __restrict__ l3_b,
    float* __restrict__ out, int out_size)
{
    __shared__ __align__(16) float hst[2][CHUNK][HPAD];
    __shared__ __align__(16) float wst[2][CHUNK][WPAD];
    __shared__ float l2s[NL2][NL1 + 1];
    __shared__ float h2s[TB][NL1 + 1];
    __shared__ float h3s[TB][NL2 + 1];
    __shared__ float l3s[NL2];

    const int tid  = threadIdx.x;
    const int row0 = blockIdx.x * TB;
    const int tx   = tid & 31;   // out pair {2tx, 2tx+1}
    const int ty   = tid >> 5;   // row quad {4ty..4ty+3}

    for (int i = tid; i < NL2 * NL1; i += T2) l2s[i >> 6][i & 63] = l2_w[i];
    if (tid < NL2) l3s[tid] = l3_w[tid];

    // h staging: TB*CHUNK/2 = 1024 half2 -> 4 per thread.
    __half2 hreg[4];
    float   wreg[16];
    {
        const int kc = 0;
#pragma unroll
        for (int u = 0; u < 4; u++) {
            int idx = tid + u * T2; int r = idx >> 5, kp = idx & 31;
            hreg[u] = *reinterpret_cast<const __half2*>(
                g_h1 + (size_t)(row0 + r) * HID2 + kc + 2 * kp);
        }
#pragma unroll
        for (int u = 0; u < 16; u++) {
            int idx = tid + u * T2; int oo = idx >> 6, kk = idx & 63;
            wreg[u] = __ldg(l1_w + (size_t)oo * HID2 + kc + kk);
        }
#pragma unroll
        for (int u = 0; u < 4; u++) {
            int idx = tid + u * T2; int r = idx >> 5, kp = idx & 31;
            float2 f = __half22float2(hreg[u]);
            hst[0][2 * kp][r]     = f.x;
            hst[0][2 * kp + 1][r] = f.y;
        }
#pragma unroll
        for (int u = 0; u < 16; u++) {
            int idx = tid + u * T2; int oo = idx >> 6, kk = idx & 63;
            wst[0][kk][oo] = wreg[u];
        }
    }
    __syncthreads();

    float acc[4][2];
#pragma unroll
    for (int i = 0; i < 4; i++) { acc[i][0] = 0.f; acc[i][1] = 0.f; }

    for (int c = 0; c < NCH; c++) {
        const int buf = c & 1;
        if (c + 1 < NCH) {
            const int kc = (c + 1) * CHUNK;
#pragma unroll
            for (int u = 0; u < 4; u++) {
                int idx = tid + u * T2; int r = idx >> 5, kp = idx & 31;
                hreg[u] = *reinterpret_cast<const __half2*>(
                    g_h1 + (size_t)(row0 + r) * HID2 + kc + 2 * kp);
            }
#pragma unroll
            for (int u = 0; u < 16; u++) {
                int idx = tid + u * T2; int oo = idx >> 6, kk = idx & 63;
                wreg[u] = __ldg(l1_w + (size_t)oo * HID2 + kc + kk);
            }
        }
#pragma unroll 16
        for (int k = 0; k < CHUNK; k++) {
            const float4 h = *reinterpret_cast<const float4*>(&hst[buf][k][4 * ty]);
            const float2 w = *reinterpret_cast<const float2*>(&wst[buf][k][2 * tx]);
            acc[0][0] = fmaf(h.x, w.x, acc[0][0]); acc[0][1] = fmaf(h.x, w.y, acc[0][1]);
            acc[1][0] = fmaf(h.y, w.x, acc[1][0]); acc[1][1] = fmaf(h.y, w.y, acc[1][1]);
            acc[2][0] = fmaf(h.z, w.x, acc[2][0]); acc[2][1] = fmaf(h.z, w.y, acc[2][1]);
            acc[3][0] = fmaf(h.w, w.x, acc[3][0]); acc[3][1] = fmaf(h.w, w.y, acc[3][1]);
        }
        if (c + 1 < NCH) {
            const int nb = (c + 1) & 1;
#pragma unroll
            for (int u = 0; u < 4; u++) {
                int idx = tid + u * T2; int r = idx >> 5, kp = idx & 31;
                float2 f = __half22float2(hreg[u]);
                hst[nb][2 * kp][r]     = f.x;
                hst[nb][2 * kp + 1][r] = f.y;
            }
#pragma unroll
            for (int u = 0; u < 16; u++) {
                int idx = tid + u * T2; int oo = idx >> 6, kk = idx & 63;
                wst[nb][kk][oo] = wreg[u];
            }
        }
        __syncthreads();
    }

    // h2 = clip(l1 out + bias)
#pragma unroll
    for (int i = 0; i < 4; i++) {
#pragma unroll
        for (int j = 0; j < 2; j++) {
            float v = acc[i][j] + __ldg(l1_b + 2 * tx + j);
            h2s[4 * ty + i][2 * tx + j] = fminf(fmaxf(v, 0.f), 1.f);
        }
    }
    __syncthreads();

    // l2
    for (int p = tid; p < TB * NL2; p += T2) {
        int r = p >> 5, oo = p & 31;
        float s = __ldg(l2_b + oo);
#pragma unroll
        for (int k = 0; k < NL1; k++) s = fmaf(h2s[r][k], l2s[oo][k], s);
        h3s[r][oo] = fminf(fmaxf(s, 0.f), 1.f);
    }
    __syncthreads();

    // l3 + sigmoid
    if (tid < TB) {
        float s = __ldg(l3_b);
#pragma unroll
        for (int k = 0; k < NL2; k++) s = fmaf(h3s[tid][k], l3s[k], s);
        float sig = 1.f / (1.f + expf(-s));
        int r = row0 + tid;
        if (out_size >= 2 * BATCH) {
            out[r]         = sig;
            out[BATCH + r] = s;
        } else {
            out[r] = sig;
        }
    }
}

// =========================================================================
extern "C" void kernel_launch(void* const* d_in, const int* in_sizes, int n_in,
                              void* d_out, int out_size)
{
    const float* wf    = (const float*)d_in[0];
    const float* bfeat = (const float*)d_in[1];
    const float* stm   = (const float*)d_in[2];
    const float* ft_w  = (const float*)d_in[3];
    const float* ft_b  = (const float*)d_in[4];
    const float* l1_w  = (const float*)d_in[5];
    const float* l1_b  = (const float*)d_in[6];
    const float* l2_w  = (const float*)d_in[7];
    const float* l2_b  = (const float*)d_in[8];
    const float* l3_w  = (const float*)d_in[9];
    const float* l3_b  = (const float*)d_in[10];
    float* out = (float*)d_out;

    dim3 tgrid(FEAT / 32, HID / 64);
    transpose_ftw<<<tgrid, 256>>>(ft_w);
    ft_kernel<<<BATCH, T1>>>(wf, bfeat, stm, ft_b);
    mlp_kernel<<<BATCH / TB, T2>>>(l1_w, l1_b, l2_w, l2_b, l3_w, l3_b, out, out_size);
}

// round 4
// speedup vs baseline: 8.0661x; 1.0263x over previous
#include <cuda_runtime.h>
#include <cuda_fp16.h>
#include <math.h>

#define BATCH 4096
#define FEAT  40960
#define HID   1024
#define HID2  2048
#define NL1   64
#define NL2   32

// ---------------- static device scratch (no allocs allowed) ----------------
__device__ __half g_h1[(size_t)BATCH * HID2];   // 16.8 MB: clipped FT output (fp16)
__device__ __half g_ftT[(size_t)FEAT * HID];    // 83.9 MB: ft_w^T [FEAT][HID] fp16 (L2-resident)
__device__ int    g_done;                       // transpose-completion counter

// =========================================================================
// Kernel R: reset the completion counter (runs first every launch)
// =========================================================================
__global__ void reset_kernel() { g_done = 0; }

// =========================================================================
// Mega-kernel: CTAs [0, NT) transpose ft_w -> g_ftT (fp16).
//              CTAs [NT, NT+BATCH) scan their feature row, spin until the
//              transpose is complete, then gather + write h1.
// =========================================================================
#define T1      256
#define NT      512
#define MAXIDX  256
#define NTILE_F (FEAT / 32)     // 1280
#define NTILES  (NTILE_F * (HID / 64))  // 20480

__global__ __launch_bounds__(T1) void mega_kernel(
    const float* __restrict__ wf,    // [B, FEAT]
    const float* __restrict__ bfeat, // [B, FEAT]
    const float* __restrict__ stm,   // [B, 1]
    const float* __restrict__ ftw,   // [HID, FEAT]
    const float* __restrict__ ft_b)  // [HID]
{
    __shared__ union {
        float tile[64][33];                       // transpose staging (8.4 KB)
        struct { int idxW[MAXIDX]; int idxB[MAXIDX]; int cw; int cb; } s;
    } sm;

    const int tid = threadIdx.x;

    if (blockIdx.x < NT) {
        // ---------------- transpose: 40 tiles of 64h x 32f per CTA ----------------
        for (int t = blockIdx.x; t < NTILES; t += NT) {
            const int f0 = (t % NTILE_F) * 32;
            const int h0 = (t / NTILE_F) * 64;
#pragma unroll
            for (int u = 0; u < 8; u++) {
                int idx = tid + u * T1;
                int hl = idx >> 5, fl = idx & 31;
                sm.tile[hl][fl] = __ldcs(ftw + (size_t)(h0 + hl) * FEAT + f0 + fl);
            }
            __syncthreads();
#pragma unroll
            for (int u = 0; u < 4; u++) {
                int idx = tid + u * T1;
                int fl = idx >> 5, hp = idx & 31;
                __half2 v = __floats2half2_rn(sm.tile[2 * hp][fl], sm.tile[2 * hp + 1][fl]);
                *reinterpret_cast<__half2*>(g_ftT + (size_t)(f0 + fl) * HID + h0 + 2 * hp) = v;
            }
            __syncthreads();
        }
        __threadfence();
        __syncthreads();
        if (tid == 0) atomicAdd(&g_done, 1);
        return;
    }

    // ---------------- scan + (wait) + gather ----------------
    const int b = blockIdx.x - NT;

    if (tid == 0) { sm.s.cw = 0; sm.s.cb = 0; }
    __syncthreads();

    // scan white + black (streaming float4 loads, batched 4-deep)
    {
        const float4* pw = (const float4*)(wf    + (size_t)b * FEAT);
        const float4* pb = (const float4*)(bfeat + (size_t)b * FEAT);
        for (int base = 0; base < FEAT / 4; base += 4 * T1) {
            float4 v[4], w[4];
#pragma unroll
            for (int u = 0; u < 4; u++) {
                v[u] = __ldcs(pw + base + tid + u * T1);
                w[u] = __ldcs(pb + base + tid + u * T1);
            }
#pragma unroll
            for (int u = 0; u < 4; u++) {
                int i = base + tid + u * T1;
                if (v[u].x != 0.f) { int q = atomicAdd(&sm.s.cw, 1); if (q < MAXIDX) sm.s.idxW[q] = 4*i;   }
                if (v[u].y != 0.f) { int q = atomicAdd(&sm.s.cw, 1); if (q < MAXIDX) sm.s.idxW[q] = 4*i+1; }
                if (v[u].z != 0.f) { int q = atomicAdd(&sm.s.cw, 1); if (q < MAXIDX) sm.s.idxW[q] = 4*i+2; }
                if (v[u].w != 0.f) { int q = atomicAdd(&sm.s.cw, 1); if (q < MAXIDX) sm.s.idxW[q] = 4*i+3; }
                if (w[u].x != 0.f) { int q = atomicAdd(&sm.s.cb, 1); if (q < MAXIDX) sm.s.idxB[q] = 4*i;   }
                if (w[u].y != 0.f) { int q = atomicAdd(&sm.s.cb, 1); if (q < MAXIDX) sm.s.idxB[q] = 4*i+1; }
                if (w[u].z != 0.f) { int q = atomicAdd(&sm.s.cb, 1); if (q < MAXIDX) sm.s.idxB[q] = 4*i+2; }
                if (w[u].w != 0.f) { int q = atomicAdd(&sm.s.cb, 1); if (q < MAXIDX) sm.s.idxB[q] = 4*i+3; }
            }
        }
    }
    __syncthreads();

    // wait for transpose completion (transpose CTAs are wave-1; by the time a
    // scanner reaches here it has done ~50us of work, so this rarely spins long)
    if (tid == 0) {
        while (atomicAdd(&g_done, 0) < NT) __nanosleep(128);
    }
    __syncthreads();
    __threadfence();

    // gather
    const float4 bias = *reinterpret_cast<const float4*>(ft_b + 4 * tid);
    float4 accW = bias, accB = bias;
    {
        const int nW = min(sm.s.cw, MAXIDX);
#pragma unroll 4
        for (int j = 0; j < nW; j++) {
            const uint2 raw = *reinterpret_cast<const uint2*>(
                g_ftT + (size_t)sm.s.idxW[j] * HID + 4 * tid);
            const float2 lo = __half22float2(*reinterpret_cast<const __half2*>(&raw.x));
            const float2 hi = __half22float2(*reinterpret_cast<const __half2*>(&raw.y));
            accW.x += lo.x; accW.y += lo.y; accW.z += hi.x; accW.w += hi.y;
        }
        const int nB = min(sm.s.cb, MAXIDX);
#pragma unroll 4
        for (int j = 0; j < nB; j++) {
            const uint2 raw = *reinterpret_cast<const uint2*>(
                g_ftT + (size_t)sm.s.idxB[j] * HID + 4 * tid);
            const float2 lo = __half22float2(*reinterpret_cast<const __half2*>(&raw.x));
            const float2 hi = __half22float2(*reinterpret_cast<const __half2*>(&raw.y));
            accB.x += lo.x; accB.y += lo.y; accB.z += hi.x; accB.w += hi.y;
        }
    }

    // stm select + clip + store fp16
    const float s = __ldg(stm + b);
    float4 cw, cb;
    cw.x = fminf(fmaxf(accW.x, 0.f), 1.f); cw.y = fminf(fmaxf(accW.y, 0.f), 1.f);
    cw.z = fminf(fmaxf(accW.z, 0.f), 1.f); cw.w = fminf(fmaxf(accW.w, 0.f), 1.f);
    cb.x = fminf(fmaxf(accB.x, 0.f), 1.f); cb.y = fminf(fmaxf(accB.y, 0.f), 1.f);
    cb.z = fminf(fmaxf(accB.z, 0.f), 1.f); cb.w = fminf(fmaxf(accB.w, 0.f), 1.f);

    float4 first, second;
    first.x  = s * cw.x + (1.f - s) * cb.x;  second.x = s * cb.x + (1.f - s) * cw.x;
    first.y  = s * cw.y + (1.f - s) * cb.y;  second.y = s * cb.y + (1.f - s) * cw.y;
    first.z  = s * cw.z + (1.f - s) * cb.z;  second.z = s * cb.z + (1.f - s) * cw.z;
    first.w  = s * cw.w + (1.f - s) * cb.w;  second.w = s * cb.w + (1.f - s) * cw.w;

    __half* o = g_h1 + (size_t)b * HID2;
    uint2 pf, ps;
    *reinterpret_cast<__half2*>(&pf.x) = __floats2half2_rn(first.x, first.y);
    *reinterpret_cast<__half2*>(&pf.y) = __floats2half2_rn(first.z, first.w);
    *reinterpret_cast<__half2*>(&ps.x) = __floats2half2_rn(second.x, second.y);
    *reinterpret_cast<__half2*>(&ps.y) = __floats2half2_rn(second.z, second.w);
    *reinterpret_cast<uint2*>(o + 4 * tid)       = pf;
    *reinterpret_cast<uint2*>(o + HID + 4 * tid) = ps;
}

// =========================================================================
// Kernel 2: MLP head (unchanged from round 3).
// =========================================================================
#define T2    256
#define TB    32
#define CHUNK 64
#define NCH   (HID2 / CHUNK)
#define HPAD  36
#define WPAD  66

__global__ __launch_bounds__(T2) void mlp_kernel(
    const float* __restrict__ l1_w, const float* __restrict__ l1_b,
    const float* __restrict__ l2_w, const float* __restrict__ l2_b,
    const float* __restrict__ l3_w, const float* __restrict__ l3_b,
    float* __restrict__ out, int out_size)
{
    __shared__ __align__(16) float hst[2][CHUNK][HPAD];
    __shared__ __align__(16) float wst[2][CHUNK][WPAD];
    __shared__ float l2s[NL2][NL1 + 1];
    __shared__ float h2s[TB][NL1 + 1];
    __shared__ float h3s[TB][NL2 + 1];
    __shared__ float l3s[NL2];

    const int tid  = threadIdx.x;
    const int row0 = blockIdx.x * TB;
    const int tx   = tid & 31;
    const int ty   = tid >> 5;

    for (int i = tid; i < NL2 * NL1; i += T2) l2s[i >> 6][i & 63] = l2_w[i];
    if (tid < NL2) l3s[tid] = l3_w[tid];

    __half2 hreg[4];
    float   wreg[16];
    {
        const int kc = 0;
#pragma unroll
        for (int u = 0; u < 4; u++) {
            int idx = tid + u * T2; int r = idx >> 5, kp = idx & 31;
            hreg[u] = *reinterpret_cast<const __half2*>(
                g_h1 + (size_t)(row0 + r) * HID2 + kc + 2 * kp);
        }
#pragma unroll
        for (int u = 0; u < 16; u++) {
            int idx = tid + u * T2; int oo = idx >> 6, kk = idx & 63;
            wreg[u] = __ldg(l1_w + (size_t)oo * HID2 + kc + kk);
        }
#pragma unroll
        for (int u = 0; u < 4; u++) {
            int idx = tid + u * T2; int r = idx >> 5, kp = idx & 31;
            float2 f = __half22float2(hreg[u]);
            hst[0][2 * kp][r]     = f.x;
            hst[0][2 * kp + 1][r] = f.y;
        }
#pragma unroll
        for (int u = 0; u < 16; u++) {
            int idx = tid + u * T2; int oo = idx >> 6, kk = idx & 63;
            wst[0][kk][oo] = wreg[u];
        }
    }
    __syncthreads();

    float acc[4][2];
#pragma unroll
    for (int i = 0; i < 4; i++) { acc[i][0] = 0.f; acc[i][1] = 0.f; }

    for (int c = 0; c < NCH; c++) {
        const int buf = c & 1;
        if (c + 1 < NCH) {
            const int kc = (c + 1) * CHUNK;
#pragma unroll
            for (int u = 0; u < 4; u++) {
                int idx = tid + u * T2; int r = idx >> 5, kp = idx & 31;
                hreg[u] = *reinterpret_cast<const __half2*>(
                    g_h1 + (size_t)(row0 + r) * HID2 + kc + 2 * kp);
            }
#pragma unroll
            for (int u = 0; u < 16; u++) {
                int idx = tid + u * T2; int oo = idx >> 6, kk = idx & 63;
                wreg[u] = __ldg(l1_w + (size_t)oo * HID2 + kc + kk);
            }
        }
#pragma unroll 16
        for (int k = 0; k < CHUNK; k++) {
            const float4 h = *reinterpret_cast<const float4*>(&hst[buf][k][4 * ty]);
            const float2 w = *reinterpret_cast<const float2*>(&wst[buf][k][2 * tx]);
            acc[0][0] = fmaf(h.x, w.x, acc[0][0]); acc[0][1] = fmaf(h.x, w.y, acc[0][1]);
            acc[1][0] = fmaf(h.y, w.x, acc[1][0]); acc[1][1] = fmaf(h.y, w.y, acc[1][1]);
            acc[2][0] = fmaf(h.z, w.x, acc[2][0]); acc[2][1] = fmaf(h.z, w.y, acc[2][1]);
            acc[3][0] = fmaf(h.w, w.x, acc[3][0]); acc[3][1] = fmaf(h.w, w.y, acc[3][1]);
        }
        if (c + 1 < NCH) {
            const int nb = (c + 1) & 1;
#pragma unroll
            for (int u = 0; u < 4; u++) {
                int idx = tid + u * T2; int r = idx >> 5, kp = idx & 31;
                float2 f = __half22float2(hreg[u]);
                hst[nb][2 * kp][r]     = f.x;
                hst[nb][2 * kp + 1][r] = f.y;
            }
#pragma unroll
            for (int u = 0; u < 16; u++) {
                int idx = tid + u * T2; int oo = idx >> 6, kk = idx & 63;
                wst[nb][kk][oo] = wreg[u];
            }
        }
        __syncthreads();
    }

#pragma unroll
    for (int i = 0; i < 4; i++) {
#pragma unroll
        for (int j = 0; j < 2; j++) {
            float v = acc[i][j] + __ldg(l1_b + 2 * tx + j);
            h2s[4 * ty + i][2 * tx + j] = fminf(fmaxf(v, 0.f), 1.f);
        }
    }
    __syncthreads();

    for (int p = tid; p < TB * NL2; p += T2) {
        int r = p >> 5, oo = p & 31;
        float s = __ldg(l2_b + oo);
#pragma unroll
        for (int k = 0; k < NL1; k++) s = fmaf(h2s[r][k], l2s[oo][k], s);
        h3s[r][oo] = fminf(fmaxf(s, 0.f), 1.f);
    }
    __syncthreads();

    if (tid < TB) {
        float s = __ldg(l3_b);
#pragma unroll
        for (int k = 0; k < NL2; k++) s = fmaf(h3s[tid][k], l3s[k], s);
        float sig = 1.f / (1.f + expf(-s));
        int r = row0 + tid;
        if (out_size >= 2 * BATCH) {
            out[r]         = sig;
            out[BATCH + r] = s;
        } else {
            out[r] = sig;
        }
    }
}

// =========================================================================
extern "C" void kernel_launch(void* const* d_in, const int* in_sizes, int n_in,
                              void* d_out, int out_size)
{
    const float* wf    = (const float*)d_in[0];
    const float* bfeat = (const float*)d_in[1];
    const float* stm   = (const float*)d_in[2];
    const float* ft_w  = (const float*)d_in[3];
    const float* ft_b  = (const float*)d_in[4];
    const float* l1_w  = (const float*)d_in[5];
    const float* l1_b  = (const float*)d_in[6];
    const float* l2_w  = (const float*)d_in[7];
    const float* l2_b  = (const float*)d_in[8];
    const float* l3_w  = (const float*)d_in[9];
    const float* l3_b  = (const float*)d_in[10];
    float* out = (float*)d_out;

    reset_kernel<<<1, 1>>>();
    mega_kernel<<<NT + BATCH, T1>>>(wf, bfeat, stm, ft_w, ft_b);
    mlp_kernel<<<BATCH / TB, T2>>>(l1_w, l1_b, l2_w, l2_b, l3_w, l3_b, out, out_size);
}